// round 1
// baseline (speedup 1.0000x reference)
#include <cuda_runtime.h>

// Problem constants
#define NPT   4096      // B*H*W = 4*32*32 output points
#define NOC   64        // output channels
#define NFEAT 576       // IC*K*K unfolded features (= 144 groups of 4)
#define NGRP  144
#define OBLK  4         // output channels per block in main kernel
#define PTB   128       // points per block (threads)

// Scratch (no allocations allowed -> device globals)
__device__ float    g_maxabs;
__device__ unsigned g_wpos[NOC * NFEAT];      // [o][t][g] : o*576 + t*144 + g, 4 features/word
__device__ unsigned g_wneg[NOC * NFEAT];
__device__ unsigned g_sv[4 * NGRP * NPT];     // [s][g][pt], 4 features/word

// ---------------------------------------------------------------- max |w|
__global__ void k_maxabs(const float* __restrict__ w, int n) {
    __shared__ float red[32];
    float m = 0.f;
    for (int i = threadIdx.x; i < n; i += blockDim.x)
        m = fmaxf(m, fabsf(w[i]));
    for (int o = 16; o; o >>= 1) m = fmaxf(m, __shfl_xor_sync(0xffffffffu, m, o));
    if ((threadIdx.x & 31) == 0) red[threadIdx.x >> 5] = m;
    __syncthreads();
    if (threadIdx.x < 32) {
        int nw = (blockDim.x + 31) >> 5;
        m = (threadIdx.x < nw) ? red[threadIdx.x] : 0.f;
        for (int o = 16; o; o >>= 1) m = fmaxf(m, __shfl_xor_sync(0xffffffffu, m, o));
        if (threadIdx.x == 0) g_maxabs = (m > 0.f) ? m : 1.f;
    }
}

// ------------------------------------------- weight bit-slicing + packing
__global__ void k_weights(const float* __restrict__ w) {
    int idx = blockIdx.x * blockDim.x + threadIdx.x;
    if (idx >= NOC * NGRP) return;
    int o = idx / NGRP, g = idx % NGRP;
    float ma = g_maxabs;
    unsigned pw[4] = {0,0,0,0}, nw[4] = {0,0,0,0};
#pragma unroll
    for (int j = 0; j < 4; j++) {
        int f = 4 * g + j;                       // f < 576 always
        float r  = w[o * NFEAT + f];
        float wp = fmaxf(r, 0.f);
        float wn = fmaxf(-r, 0.f);
        // replicate jax: round(wp / max_abs * 255), half-to-even
        int pi = (int)rintf(__fdiv_rn(wp, ma) * 255.f);
        int ni = (int)rintf(__fdiv_rn(wn, ma) * 255.f);
#pragma unroll
        for (int t = 0; t < 4; t++) {
            pw[t] |= (unsigned)((pi >> (2 * t)) & 3) << (8 * j);
            nw[t] |= (unsigned)((ni >> (2 * t)) & 3) << (8 * j);
        }
    }
#pragma unroll
    for (int t = 0; t < 4; t++) {
        g_wpos[o * NFEAT + t * NGRP + g] = pw[t];
        g_wneg[o * NFEAT + t * NGRP + g] = nw[t];
    }
}

// -------------- input quantize + unfold + bit-stream pack (transposed layout)
__global__ void k_streams(const float* __restrict__ x) {
    int id = blockIdx.x * blockDim.x + threadIdx.x;   // over NPT*NGRP = 589824
    if (id >= NPT * NGRP) return;
    int pt = id & (NPT - 1);
    int g  = id >> 12;
    int b = pt >> 10, p = pt & 1023, h = p >> 5, wc = p & 31;
    unsigned sw0 = 0, sw1 = 0, sw2 = 0, sw3 = 0;
#pragma unroll
    for (int j = 0; j < 4; j++) {
        int f = 4 * g + j;
        int c = f / 9, rem = f - 9 * c, kh = rem / 3, kw = rem - 3 * (rem / 3);
        int y = h + kh - 1, xx = wc + kw - 1;
        float v = 0.f;
        if ((unsigned)y < 32u && (unsigned)xx < 32u)
            v = x[((b * 64 + c) * 32 + y) * 32 + xx];
        // fixed-point quantize: clip then *16, round half-to-even, 2's complement byte
        v = fminf(fmaxf(v, -8.f), 7.9375f);
        int q = ((int)rintf(v * 16.f)) & 255;
        sw0 |= (unsigned)( q        & 3) << (8 * j);
        sw1 |= (unsigned)((q >> 2)  & 3) << (8 * j);
        sw2 |= (unsigned)((q >> 4)  & 3) << (8 * j);
        sw3 |= (unsigned)((q >> 6)  & 3) << (8 * j);
    }
    g_sv[(0 * NGRP + g) * NPT + pt] = sw0;
    g_sv[(1 * NGRP + g) * NPT + pt] = sw1;
    g_sv[(2 * NGRP + g) * NPT + pt] = sw2;
    g_sv[(3 * NGRP + g) * NPT + pt] = sw3;
}

// ---------------------------------------------------------- main dp4a MAC
__global__ __launch_bounds__(PTB) void k_main(float* __restrict__ out) {
    __shared__ unsigned s_wp[OBLK * NFEAT];
    __shared__ unsigned s_wn[OBLK * NFEAT];
    const int tid   = threadIdx.x;
    const int pt    = blockIdx.x * PTB + tid;          // 0..4095
    const int obase = blockIdx.y * OBLK;

    for (int i = tid; i < OBLK * NFEAT; i += PTB) {
        s_wp[i] = g_wpos[obase * NFEAT + i];
        s_wn[i] = g_wneg[obase * NFEAT + i];
    }
    __syncthreads();

    const float scale = g_maxabs * (1.0f / 255.0f);
    const int b = pt >> 10, p = pt & 1023;
    const unsigned* __restrict__ sv = g_sv + pt;

#pragma unroll 1
    for (int ol = 0; ol < OBLK; ol++) {
        const unsigned* wp = s_wp + ol * NFEAT;
        const unsigned* wn = s_wn + ol * NFEAT;
        int diff = 0;
#pragma unroll 1
        for (int c = 0; c < 5; c++) {
            int accp[16], accn[16];
#pragma unroll
            for (int i = 0; i < 16; i++) { accp[i] = 0; accn[i] = 0; }
            const int g0 = c * 29;
            const int g1 = (c == 4) ? NGRP : (g0 + 29);   // last chunk: 28 groups
#pragma unroll 4
            for (int g = g0; g < g1; g++) {
                unsigned a[4], wpv[4], wnv[4];
#pragma unroll
                for (int s = 0; s < 4; s++)
                    a[s] = sv[(s * NGRP + g) << 12];
#pragma unroll
                for (int t = 0; t < 4; t++) {
                    wpv[t] = wp[t * NGRP + g];
                    wnv[t] = wn[t * NGRP + g];
                }
#pragma unroll
                for (int s = 0; s < 4; s++)
#pragma unroll
                    for (int t = 0; t < 4; t++) {
                        accp[s * 4 + t] = __dp4a((int)a[s], (int)wpv[t], accp[s * 4 + t]);
                        accn[s * 4 + t] = __dp4a((int)a[s], (int)wnv[t], accn[s * 4 + t]);
                    }
            }
            // ADC clamp (x>=0 integer -> round is identity, clip at 31) + 4^(s+t) weights
#pragma unroll
            for (int s = 0; s < 4; s++)
#pragma unroll
                for (int t = 0; t < 4; t++)
                    diff += (min(accp[s * 4 + t], 31) - min(accn[s * 4 + t], 31))
                            * (1 << (2 * (s + t)));
        }
        out[((b * NOC + obase + ol) << 10) + p] = (float)diff * scale;
    }
}

// zero any tail elements of d_out beyond the conv output (scalar aux loss etc.)
__global__ void k_tail(float* __restrict__ out, int start, int total) {
    int i = start + blockIdx.x * blockDim.x + threadIdx.x;
    if (i < total) out[i] = 0.f;
}

extern "C" void kernel_launch(void* const* d_in, const int* in_sizes, int n_in,
                              void* d_out, int out_size) {
    const float* x = (const float*)d_in[0];   // inputs (4,64,32,32)
    const float* w = (const float*)d_in[1];   // weight (64,64,3,3)
    float* out = (float*)d_out;

    k_maxabs <<<1, 1024>>>(w, in_sizes[1]);
    k_weights<<<(NOC * NGRP + 255) / 256, 256>>>(w);
    k_streams<<<(NPT * NGRP + 255) / 256, 256>>>(x);
    k_main   <<<dim3(NPT / PTB, NOC / OBLK), PTB>>>(out);

    if (out_size > NPT * NOC) {
        int extra = out_size - NPT * NOC;
        k_tail<<<(extra + 255) / 256, 256>>>(out, NPT * NOC, out_size);
    }
}

// round 2
// speedup vs baseline: 1.6181x; 1.6181x over previous
#include <cuda_runtime.h>

// Problem constants
#define NPT   4096      // B*H*W = 4*32*32 output points
#define NOC   64        // output channels
#define NFEAT 576       // IC*K*K unfolded features (= 144 groups of 4)
#define NGRP  144
#define NCH   5         // subarray chunks (116 feats = 29 groups each; last 28)
#define OBLK  2         // output channels per block in main kernel
#define PTB   128       // points per block (threads)

// Scratch (no allocations allowed -> device globals)
__device__ float    g_maxabs;
__device__ unsigned g_wpos[NOC * NFEAT];        // [o][t][g]
__device__ unsigned g_wneg[NOC * NFEAT];
__device__ unsigned g_sv[4 * NGRP * NPT];       // [s][g][pt]
__device__ int      g_part[NCH * NOC * NPT];    // per-chunk partial diffs

// ---------------------------------------------------------------- max |w|
__global__ void k_maxabs(const float* __restrict__ w, int n) {
    __shared__ float red[32];
    float m = 0.f;
    for (int i = threadIdx.x; i < n; i += blockDim.x)
        m = fmaxf(m, fabsf(w[i]));
    for (int o = 16; o; o >>= 1) m = fmaxf(m, __shfl_xor_sync(0xffffffffu, m, o));
    if ((threadIdx.x & 31) == 0) red[threadIdx.x >> 5] = m;
    __syncthreads();
    if (threadIdx.x < 32) {
        int nw = (blockDim.x + 31) >> 5;
        m = (threadIdx.x < nw) ? red[threadIdx.x] : 0.f;
        for (int o = 16; o; o >>= 1) m = fmaxf(m, __shfl_xor_sync(0xffffffffu, m, o));
        if (threadIdx.x == 0) g_maxabs = (m > 0.f) ? m : 1.f;
    }
}

// ------------------------------------------- weight bit-slicing + packing
__global__ void k_weights(const float* __restrict__ w) {
    int idx = blockIdx.x * blockDim.x + threadIdx.x;
    if (idx >= NOC * NGRP) return;
    int o = idx / NGRP, g = idx % NGRP;
    float ma = g_maxabs;
    unsigned pw[4] = {0,0,0,0}, nw[4] = {0,0,0,0};
#pragma unroll
    for (int j = 0; j < 4; j++) {
        int f = 4 * g + j;
        float r  = w[o * NFEAT + f];
        float wp = fmaxf(r, 0.f);
        float wn = fmaxf(-r, 0.f);
        int pi = (int)rintf(__fdiv_rn(wp, ma) * 255.f);
        int ni = (int)rintf(__fdiv_rn(wn, ma) * 255.f);
#pragma unroll
        for (int t = 0; t < 4; t++) {
            pw[t] |= (unsigned)((pi >> (2 * t)) & 3) << (8 * j);
            nw[t] |= (unsigned)((ni >> (2 * t)) & 3) << (8 * j);
        }
    }
#pragma unroll
    for (int t = 0; t < 4; t++) {
        g_wpos[o * NFEAT + t * NGRP + g] = pw[t];
        g_wneg[o * NFEAT + t * NGRP + g] = nw[t];
    }
}

// -------------- input quantize + unfold + bit-stream pack (transposed layout)
__global__ void k_streams(const float* __restrict__ x) {
    int id = blockIdx.x * blockDim.x + threadIdx.x;   // over NPT*NGRP
    if (id >= NPT * NGRP) return;
    int pt = id & (NPT - 1);
    int g  = id >> 12;
    int b = pt >> 10, p = pt & 1023, h = p >> 5, wc = p & 31;
    unsigned sw0 = 0, sw1 = 0, sw2 = 0, sw3 = 0;
#pragma unroll
    for (int j = 0; j < 4; j++) {
        int f = 4 * g + j;
        int c = f / 9, rem = f - 9 * c, kh = rem / 3, kw = rem - 3 * (rem / 3);
        int y = h + kh - 1, xx = wc + kw - 1;
        float v = 0.f;
        if ((unsigned)y < 32u && (unsigned)xx < 32u)
            v = x[((b * 64 + c) * 32 + y) * 32 + xx];
        v = fminf(fmaxf(v, -8.f), 7.9375f);
        int q = ((int)rintf(v * 16.f)) & 255;
        sw0 |= (unsigned)( q        & 3) << (8 * j);
        sw1 |= (unsigned)((q >> 2)  & 3) << (8 * j);
        sw2 |= (unsigned)((q >> 4)  & 3) << (8 * j);
        sw3 |= (unsigned)((q >> 6)  & 3) << (8 * j);
    }
    g_sv[(0 * NGRP + g) * NPT + pt] = sw0;
    g_sv[(1 * NGRP + g) * NPT + pt] = sw1;
    g_sv[(2 * NGRP + g) * NPT + pt] = sw2;
    g_sv[(3 * NGRP + g) * NPT + pt] = sw3;
}

// ---------------------------------------------------------- main dp4a MAC
// grid: (NPT/PTB, NOC/OBLK, NCH). Each block: 128 points x OBLK oc x 1 chunk.
__global__ __launch_bounds__(PTB) void k_main() {
    __shared__ unsigned s_wp[OBLK * 4 * 29];
    __shared__ unsigned s_wn[OBLK * 4 * 29];
    const int tid   = threadIdx.x;
    const int pt    = blockIdx.x * PTB + tid;
    const int obase = blockIdx.y * OBLK;
    const int c     = blockIdx.z;
    const int g0    = c * 29;
    const int ng    = (c == 4) ? 28 : 29;

    // stage this chunk's weights: [ol][t][gl]
    for (int i = tid; i < OBLK * 4 * ng; i += PTB) {
        int gl = i % ng, r = i / ng;          // r = ol*4 + t
        int t = r & 3, ol = r >> 2;
        s_wp[(ol * 4 + t) * 29 + gl] = g_wpos[(obase + ol) * NFEAT + t * NGRP + g0 + gl];
        s_wn[(ol * 4 + t) * 29 + gl] = g_wneg[(obase + ol) * NFEAT + t * NGRP + g0 + gl];
    }
    __syncthreads();

    const unsigned* __restrict__ sv = g_sv + ((long)g0 << 12) + pt;

#pragma unroll
    for (int ol = 0; ol < OBLK; ol++) {
        const unsigned* wp = s_wp + ol * 4 * 29;
        const unsigned* wn = s_wn + ol * 4 * 29;
        int accp[16], accn[16];
#pragma unroll
        for (int i = 0; i < 16; i++) { accp[i] = 0; accn[i] = 0; }
#pragma unroll 4
        for (int gl = 0; gl < ng; gl++) {
            unsigned a[4], wpv[4], wnv[4];
#pragma unroll
            for (int s = 0; s < 4; s++)
                a[s] = sv[((s * NGRP + gl) << 12)];
#pragma unroll
            for (int t = 0; t < 4; t++) {
                wpv[t] = wp[t * 29 + gl];
                wnv[t] = wn[t * 29 + gl];
            }
#pragma unroll
            for (int s = 0; s < 4; s++)
#pragma unroll
                for (int t = 0; t < 4; t++) {
                    accp[s * 4 + t] = __dp4a((int)a[s], (int)wpv[t], accp[s * 4 + t]);
                    accn[s * 4 + t] = __dp4a((int)a[s], (int)wnv[t], accn[s * 4 + t]);
                }
        }
        int diff = 0;
#pragma unroll
        for (int s = 0; s < 4; s++)
#pragma unroll
            for (int t = 0; t < 4; t++)
                diff += (min(accp[s * 4 + t], 31) - min(accn[s * 4 + t], 31))
                        << (2 * (s + t));
        g_part[((c * NOC + obase + ol) << 12) + pt] = diff;
    }
}

// -------------------------------------------- combine partials + scale
__global__ void k_final(float* __restrict__ out) {
    int id = blockIdx.x * blockDim.x + threadIdx.x;   // NOC*NPT
    if (id >= NOC * NPT) return;
    int oc = id >> 12, pt = id & (NPT - 1);
    int b = pt >> 10, p = pt & 1023;
    int d = 0;
#pragma unroll
    for (int c = 0; c < NCH; c++)
        d += g_part[((c * NOC + oc) << 12) + pt];
    out[((b * NOC + oc) << 10) + p] = (float)d * (g_maxabs * (1.0f / 255.0f));
}

// zero any tail elements of d_out beyond the conv output
__global__ void k_tail(float* __restrict__ out, int start, int total) {
    int i = start + blockIdx.x * blockDim.x + threadIdx.x;
    if (i < total) out[i] = 0.f;
}

extern "C" void kernel_launch(void* const* d_in, const int* in_sizes, int n_in,
                              void* d_out, int out_size) {
    const float* x = (const float*)d_in[0];   // inputs (4,64,32,32)
    const float* w = (const float*)d_in[1];   // weight (64,64,3,3)
    float* out = (float*)d_out;

    k_maxabs <<<1, 1024>>>(w, in_sizes[1]);
    k_weights<<<(NOC * NGRP + 255) / 256, 256>>>(w);
    k_streams<<<(NPT * NGRP + 255) / 256, 256>>>(x);
    k_main   <<<dim3(NPT / PTB, NOC / OBLK, NCH), PTB>>>();
    k_final  <<<(NOC * NPT + 255) / 256, 256>>>(out);

    if (out_size > NPT * NOC) {
        int extra = out_size - NPT * NOC;
        k_tail<<<(extra + 255) / 256, 256>>>(out, NPT * NOC, out_size);
    }
}

// round 3
// speedup vs baseline: 1.6372x; 1.0118x over previous
#include <cuda_runtime.h>

// Problem constants
#define NPT   4096      // B*H*W = 4*32*32 output points
#define NOC   64        // output channels
#define NFEAT 576       // IC*K*K unfolded features (= 144 groups of 4)
#define NGRP  144
#define NCH   5         // subarray chunks (29,29,29,29,28 groups)
#define OBLK  4         // output channels per block in main kernel
#define PTB   128       // points per block (threads)

// Scratch (no allocations allowed -> device globals)
__device__ float    g_maxabs;
__device__ unsigned g_wpos[NOC * NFEAT];        // [o][t][g]
__device__ unsigned g_wneg[NOC * NFEAT];
__device__ uint4    g_sv2[NGRP * NPT];          // [g][pt] -> 4 stream words
__device__ int      g_part[NCH * NOC * NPT];    // per-chunk partial diffs

// ---------------------------------------------------------------- max |w|
__global__ void k_maxabs(const float* __restrict__ w, int n) {
    __shared__ float red[32];
    float m = 0.f;
    for (int i = threadIdx.x; i < n; i += blockDim.x)
        m = fmaxf(m, fabsf(w[i]));
    for (int o = 16; o; o >>= 1) m = fmaxf(m, __shfl_xor_sync(0xffffffffu, m, o));
    if ((threadIdx.x & 31) == 0) red[threadIdx.x >> 5] = m;
    __syncthreads();
    if (threadIdx.x < 32) {
        int nw = (blockDim.x + 31) >> 5;
        m = (threadIdx.x < nw) ? red[threadIdx.x] : 0.f;
        for (int o = 16; o; o >>= 1) m = fmaxf(m, __shfl_xor_sync(0xffffffffu, m, o));
        if (threadIdx.x == 0) g_maxabs = (m > 0.f) ? m : 1.f;
    }
}

// ------------------------------------------- weight bit-slicing + packing
__global__ void k_weights(const float* __restrict__ w) {
    int idx = blockIdx.x * blockDim.x + threadIdx.x;
    if (idx >= NOC * NGRP) return;
    int o = idx / NGRP, g = idx % NGRP;
    float ma = g_maxabs;
    unsigned pw[4] = {0,0,0,0}, nw[4] = {0,0,0,0};
#pragma unroll
    for (int j = 0; j < 4; j++) {
        int f = 4 * g + j;
        float r  = w[o * NFEAT + f];
        float wp = fmaxf(r, 0.f);
        float wn = fmaxf(-r, 0.f);
        int pi = (int)rintf(__fdiv_rn(wp, ma) * 255.f);
        int ni = (int)rintf(__fdiv_rn(wn, ma) * 255.f);
#pragma unroll
        for (int t = 0; t < 4; t++) {
            pw[t] |= (unsigned)((pi >> (2 * t)) & 3) << (8 * j);
            nw[t] |= (unsigned)((ni >> (2 * t)) & 3) << (8 * j);
        }
    }
#pragma unroll
    for (int t = 0; t < 4; t++) {
        g_wpos[o * NFEAT + t * NGRP + g] = pw[t];
        g_wneg[o * NFEAT + t * NGRP + g] = nw[t];
    }
}

// -------------- input quantize + unfold + bit-stream pack ([g][pt] uint4)
__global__ void k_streams(const float* __restrict__ x) {
    int id = blockIdx.x * blockDim.x + threadIdx.x;   // over NPT*NGRP
    if (id >= NPT * NGRP) return;
    int pt = id & (NPT - 1);
    int g  = id >> 12;
    int b = pt >> 10, p = pt & 1023, h = p >> 5, wc = p & 31;
    unsigned sw0 = 0, sw1 = 0, sw2 = 0, sw3 = 0;
#pragma unroll
    for (int j = 0; j < 4; j++) {
        int f = 4 * g + j;
        int c = f / 9, rem = f - 9 * c, kh = rem / 3, kw = rem - 3 * (rem / 3);
        int y = h + kh - 1, xx = wc + kw - 1;
        float v = 0.f;
        if ((unsigned)y < 32u && (unsigned)xx < 32u)
            v = x[((b * 64 + c) * 32 + y) * 32 + xx];
        v = fminf(fmaxf(v, -8.f), 7.9375f);
        int q = ((int)rintf(v * 16.f)) & 255;
        sw0 |= (unsigned)( q        & 3) << (8 * j);
        sw1 |= (unsigned)((q >> 2)  & 3) << (8 * j);
        sw2 |= (unsigned)((q >> 4)  & 3) << (8 * j);
        sw3 |= (unsigned)((q >> 6)  & 3) << (8 * j);
    }
    g_sv2[g * NPT + pt] = make_uint4(sw0, sw1, sw2, sw3);
}

// ---------------------------------------------------------- main dp4a MAC
// grid: (NPT/PTB, NOC/OBLK, NCH). Block: 128 points x OBLK oc x 1 chunk.
__global__ __launch_bounds__(PTB) void k_main() {
    // [ol][gl][0..3]=pos t0..t3, [4..7]=neg t0..t3  (16B aligned rows)
    __shared__ unsigned s_w[OBLK][29][8];
    const int tid   = threadIdx.x;
    const int pt    = blockIdx.x * PTB + tid;
    const int obase = blockIdx.y * OBLK;
    const int c     = blockIdx.z;
    const int g0    = c * 29;
    const int ng    = (c == 4) ? 28 : 29;

    for (int i = tid; i < OBLK * 29 * 8; i += PTB) {
        int r = i & 7, rest = i >> 3;
        int gl = rest % 29, ol = rest / 29;
        unsigned v = 0;
        if (gl < ng) {
            const unsigned* src = (r < 4) ? g_wpos : g_wneg;
            v = src[(obase + ol) * NFEAT + (r & 3) * NGRP + g0 + gl];
        }
        s_w[ol][gl][r] = v;
    }
    __syncthreads();

    const uint4* __restrict__ sv = g_sv2 + g0 * NPT + pt;

#pragma unroll 1
    for (int ol = 0; ol < OBLK; ol++) {
        int accp[16], accn[16];
#pragma unroll
        for (int i = 0; i < 16; i++) { accp[i] = 0; accn[i] = 0; }
#pragma unroll 2
        for (int gl = 0; gl < ng; gl++) {
            uint4 a  = sv[gl * NPT];                              // LDG.128
            uint4 wp = *reinterpret_cast<const uint4*>(&s_w[ol][gl][0]);  // LDS.128
            uint4 wn = *reinterpret_cast<const uint4*>(&s_w[ol][gl][4]);  // LDS.128
            unsigned av[4] = {a.x, a.y, a.z, a.w};
            unsigned pv[4] = {wp.x, wp.y, wp.z, wp.w};
            unsigned nv[4] = {wn.x, wn.y, wn.z, wn.w};
#pragma unroll
            for (int s = 0; s < 4; s++)
#pragma unroll
                for (int t = 0; t < 4; t++) {
                    accp[s * 4 + t] = __dp4a((int)av[s], (int)pv[t], accp[s * 4 + t]);
                    accn[s * 4 + t] = __dp4a((int)av[s], (int)nv[t], accn[s * 4 + t]);
                }
        }
        int diff = 0;
#pragma unroll
        for (int s = 0; s < 4; s++)
#pragma unroll
            for (int t = 0; t < 4; t++)
                diff += (min(accp[s * 4 + t], 31) - min(accn[s * 4 + t], 31))
                        << (2 * (s + t));
        g_part[((c * NOC + obase + ol) << 12) + pt] = diff;
    }
}

// -------------------------------------------- combine partials + scale
__global__ void k_final(float* __restrict__ out) {
    int id = blockIdx.x * blockDim.x + threadIdx.x;   // NOC*NPT
    if (id >= NOC * NPT) return;
    int oc = id >> 12, pt = id & (NPT - 1);
    int b = pt >> 10, p = pt & 1023;
    int d = 0;
#pragma unroll
    for (int c = 0; c < NCH; c++)
        d += g_part[((c * NOC + oc) << 12) + pt];
    out[((b * NOC + oc) << 10) + p] = (float)d * (g_maxabs * (1.0f / 255.0f));
}

// zero any tail elements of d_out beyond the conv output
__global__ void k_tail(float* __restrict__ out, int start, int total) {
    int i = start + blockIdx.x * blockDim.x + threadIdx.x;
    if (i < total) out[i] = 0.f;
}

extern "C" void kernel_launch(void* const* d_in, const int* in_sizes, int n_in,
                              void* d_out, int out_size) {
    const float* x = (const float*)d_in[0];   // inputs (4,64,32,32)
    const float* w = (const float*)d_in[1];   // weight (64,64,3,3)
    float* out = (float*)d_out;

    k_maxabs <<<1, 1024>>>(w, in_sizes[1]);
    k_weights<<<(NOC * NGRP + 255) / 256, 256>>>(w);
    k_streams<<<(NPT * NGRP + 255) / 256, 256>>>(x);
    k_main   <<<dim3(NPT / PTB, NOC / OBLK, NCH), PTB>>>();
    k_final  <<<(NOC * NPT + 255) / 256, 256>>>(out);

    if (out_size > NPT * NOC) {
        int extra = out_size - NPT * NOC;
        k_tail<<<(extra + 255) / 256, 256>>>(out, NPT * NOC, out_size);
    }
}